// round 15
// baseline (speedup 1.0000x reference)
#include <cuda_runtime.h>
#include <cuda_fp16.h>
#include <cstdint>

// Problem constants (C=32,H=32,W=32,KS=3, B=32)
constexpr int NDIM = 32 * 32 * 32 + 1;   // 32769
constexpr int KDIM = 32 * 3 * 3;         // 288
constexpr int BDIM = 32;

constexpr int WARPS_PER_BLOCK = 8;
constexpr int NBLK = (NDIM + WARPS_PER_BLOCK - 1) / WARPS_PER_BLOCK;  // 4097
constexpr int QCNT = KDIM / 32;                                        // 9

// x transposed to [N, B] in fp16: 64 B rows; one LDG.128 with 4-lane groups
// gathers EIGHT different rows per instruction.
__device__ __align__(16) __half g_xT[(size_t)NDIM * BDIM];

// L2-only loads (bypass L1) for the single-use feed streams: keeps L1
// exclusively populated by x_T gather lines (worth ~1 us, measured R14).
__device__ __forceinline__ int4 ldcg_int4(const int4* p)
{
    int4 r;
    asm volatile("ld.global.cg.v4.s32 {%0,%1,%2,%3}, [%4];"
                 : "=r"(r.x), "=r"(r.y), "=r"(r.z), "=r"(r.w) : "l"(p));
    return r;
}
__device__ __forceinline__ float4 ldcg_float4(const float4* p)
{
    float4 r;
    asm volatile("ld.global.cg.v4.f32 {%0,%1,%2,%3}, [%4];"
                 : "=f"(r.x), "=f"(r.y), "=f"(r.z), "=f"(r.w) : "l"(p));
    return r;
}

// ---------------------------------------------------------------------------
// Kernel 1: transpose + fp16-convert x [B, N] -> x_T [N, B].
// Coalesced scalar loads (NDIM odd), smem staging at 80B stride, one uint4
// store per thread -> fully packed 128B store lines.
// ---------------------------------------------------------------------------
constexpr int TP_STRIDE = 40;   // halves per smem row (80 B, 16B-aligned)

__global__ __launch_bounds__(256) void transpose_kernel(const float* __restrict__ x)
{
    __shared__ __half tile[64][TP_STRIDE];

    const int n0 = blockIdx.x * 64;
    const int t  = threadIdx.x;

    #pragma unroll
    for (int i = 0; i < 8; ++i) {
        const int idx = i * 256 + t;
        const int b   = idx >> 6;
        const int nl  = idx & 63;
        const int n   = n0 + nl;
        if (n < NDIM)
            tile[nl][b] = __float2half(x[(size_t)b * NDIM + n]);
    }
    __syncthreads();

    const int nl   = t >> 2;
    const int quad = t & 3;
    const int n    = n0 + nl;
    if (n < NDIM) {
        uint4 u = *(const uint4*)&tile[nl][quad * 8];
        *(uint4*)((char*)g_xT + (size_t)n * 64 + quad * 16) = u;
    }
}

// ---------------------------------------------------------------------------
// Kernel 2: one warp per output row n, 4097 blocks.
//   g = lane>>2 : k within a 32-k chunk; quad = lane&3 : 16B slice of row.
// Feed: one int4 + one float4 per group per q via ld.global.cg (L2-only).
// Gather: 4 LDG.128 (__ldg, L1-cached) per group per q, 8 fp16 rows each.
// Runs AT the LTS sector cap (~6300 B/cyc of L2->SM traffic) — the measured
// structural floor for random gathers at B=32 / fp16 precision.
// Last q-iteration peeled: hot loop carries no feed-prefetch predicate.
// ---------------------------------------------------------------------------
__device__ __forceinline__ void fma8(float* acc, float v, uint4 h)
{
    float2 f0 = __half22float2(*(const __half2*)&h.x);
    float2 f1 = __half22float2(*(const __half2*)&h.y);
    float2 f2 = __half22float2(*(const __half2*)&h.z);
    float2 f3 = __half22float2(*(const __half2*)&h.w);
    acc[0] = fmaf(v, f0.x, acc[0]); acc[1] = fmaf(v, f0.y, acc[1]);
    acc[2] = fmaf(v, f1.x, acc[2]); acc[3] = fmaf(v, f1.y, acc[3]);
    acc[4] = fmaf(v, f2.x, acc[4]); acc[5] = fmaf(v, f2.y, acc[5]);
    acc[6] = fmaf(v, f3.x, acc[6]); acc[7] = fmaf(v, f3.y, acc[7]);
}

__global__ __launch_bounds__(WARPS_PER_BLOCK * 32, 4)
void gather_dot_kernel(const float* __restrict__ vals,
                       const int*   __restrict__ cols,
                       float*       __restrict__ out)
{
    __shared__ float s_acc[WARPS_PER_BLOCK][33];   // [n_off][b], padded

    const int w    = threadIdx.x >> 5;
    const int lane = threadIdx.x & 31;
    const int g    = lane >> 2;   // group 0..7
    const int quad = lane & 3;    // 16B slice -> b = quad*8 .. quad*8+7
    const int n    = blockIdx.x * WARPS_PER_BLOCK + w;

    float acc[8] = {0.f, 0.f, 0.f, 0.f, 0.f, 0.f, 0.f, 0.f};

    if (n < NDIM) {
        const int4*   cp = (const int4*)  (cols + (size_t)n * KDIM) + g;
        const float4* vp = (const float4*)(vals + (size_t)n * KDIM) + g;
        const char*   xb = (const char*)g_xT + quad * 16;

        int4   c = ldcg_int4(cp);          // feed q=0 (L2-only)
        float4 v = ldcg_float4(vp);

        #pragma unroll
        for (int q = 0; q < QCNT - 1; ++q) {
            // 4 independent gathers for this q (the cap-bound stream)
            uint4 h0 = __ldg((const uint4*)(xb + ((size_t)(unsigned)c.x << 6)));
            uint4 h1 = __ldg((const uint4*)(xb + ((size_t)(unsigned)c.y << 6)));
            uint4 h2 = __ldg((const uint4*)(xb + ((size_t)(unsigned)c.z << 6)));
            uint4 h3 = __ldg((const uint4*)(xb + ((size_t)(unsigned)c.w << 6)));
            float4 vc = v;

            // unconditional feed prefetch for q+1 (loop bound excludes last q)
            c = ldcg_int4(cp + (q + 1) * 8);
            v = ldcg_float4(vp + (q + 1) * 8);

            fma8(acc, vc.x, h0);
            fma8(acc, vc.y, h1);
            fma8(acc, vc.z, h2);
            fma8(acc, vc.w, h3);
        }
        // peeled last iteration: no prefetch
        {
            uint4 h0 = __ldg((const uint4*)(xb + ((size_t)(unsigned)c.x << 6)));
            uint4 h1 = __ldg((const uint4*)(xb + ((size_t)(unsigned)c.y << 6)));
            uint4 h2 = __ldg((const uint4*)(xb + ((size_t)(unsigned)c.z << 6)));
            uint4 h3 = __ldg((const uint4*)(xb + ((size_t)(unsigned)c.w << 6)));
            fma8(acc, v.x, h0);
            fma8(acc, v.y, h1);
            fma8(acc, v.z, h2);
            fma8(acc, v.w, h3);
        }
    }

    // Butterfly-reduce over the 8 groups (lane bits [2:4]).
    #pragma unroll
    for (int s = 4; s < 32; s <<= 1) {
        #pragma unroll
        for (int j = 0; j < 8; ++j)
            acc[j] += __shfl_xor_sync(0xffffffffu, acc[j], s);
    }

    // Lanes 0..3 hold final sums for b = quad*8 + j.
    if (lane < 4) {
        #pragma unroll
        for (int j = 0; j < 8; ++j)
            s_acc[w][lane * 8 + j] = acc[j];
    }
    __syncthreads();

    // Sector-coalesced store: thread t -> b = t/8, j = t%8 (8 consecutive n).
    const int b  = threadIdx.x >> 3;
    const int j  = threadIdx.x & 7;
    const int nn = blockIdx.x * WARPS_PER_BLOCK + j;
    if (nn < NDIM)
        out[(size_t)b * NDIM + nn] = s_acc[j][b];
}

// ---------------------------------------------------------------------------
// kernel_launch: inputs per metadata order: x_affine (f32), vals (f32), cols (i32)
// ---------------------------------------------------------------------------
extern "C" void kernel_launch(void* const* d_in, const int* in_sizes, int n_in,
                              void* d_out, int out_size)
{
    const float* x    = (const float*)d_in[0];
    const float* vals = (const float*)d_in[1];
    const int*   cols = (const int*)  d_in[2];
    float*       out  = (float*)d_out;

    (void)in_sizes; (void)n_in; (void)out_size;

    {
        int grid = (NDIM + 63) / 64;   // 513 blocks, 256 threads
        transpose_kernel<<<grid, 256>>>(x);
    }
    {
        gather_dot_kernel<<<NBLK, WARPS_PER_BLOCK * 32>>>(vals, cols, out);
    }
}